// round 3
// baseline (speedup 1.0000x reference)
#include <cuda_runtime.h>
#include <math_constants.h>

#define BATCH   32
#define SEQ     8192
#define HID     256
#define NSPLIT  32
#define CHUNK   (SEQ / NSPLIT)   // 256
#define WARPS   8
#define ITERS   (CHUNK / WARPS)  // 32

// Scratch (allocation-free rule: __device__ globals)
__device__ float g_pm[BATCH * NSPLIT];
__device__ float g_pl[BATCH * NSPLIT];
__device__ float g_pctx[BATCH * NSPLIT * HID];
__device__ float g_M[BATCH];
__device__ float g_L[BATCH];

// Kernel 1: fused score + online softmax + context partials.
// grid (BATCH, NSPLIT), block 256. Each warp processes ITERS s-rows,
// with a 2-deep software prefetch ring (4 outstanding LDG.128 per lane).
__global__ __launch_bounds__(256) void attn_pass1(
    const float* __restrict__ dec,   // (B, H)
    const float* __restrict__ enc,   // (B, S, H)
    float* __restrict__ score_out)   // (B, S) raw scores (normalized later)
{
    const int b     = blockIdx.x;
    const int chunk = blockIdx.y;
    const int tid   = threadIdx.x;
    const int wid   = tid >> 5;
    const int lane  = tid & 31;

    __shared__ float sdec[HID];
    __shared__ float sm[WARPS];
    __shared__ float sl[WARPS];
    __shared__ float sctx[WARPS][HID];

    sdec[tid] = dec[b * HID + tid];
    __syncthreads();

    const float4 d0 = *(const float4*)&sdec[lane * 4];
    const float4 d1 = *(const float4*)&sdec[128 + lane * 4];

    const float* encb = enc + (size_t)b * SEQ * HID + (size_t)chunk * CHUNK * HID;

    float m = -CUDART_INF_F;
    float l = 0.f;
    float c0x = 0.f, c0y = 0.f, c0z = 0.f, c0w = 0.f;
    float c1x = 0.f, c1y = 0.f, c1z = 0.f, c1w = 0.f;

    // 2-deep prefetch ring: rows for it=0 and it=1 in flight before the loop
    const float* r0 = encb + (size_t)wid * HID;
    const float* r1 = encb + (size_t)(wid + WARPS) * HID;
    float4 p0a = *(const float4*)&r0[lane * 4];
    float4 p0b = *(const float4*)&r0[128 + lane * 4];
    float4 p1a = *(const float4*)&r1[lane * 4];
    float4 p1b = *(const float4*)&r1[128 + lane * 4];

    #pragma unroll 4
    for (int it = 0; it < ITERS; ++it) {
        const int s = wid + it * WARPS;     // s within chunk
        const float4 a0 = p0a;
        const float4 a1 = p0b;
        // rotate ring and issue prefetch for it+2
        p0a = p1a;  p0b = p1b;
        if (it + 2 < ITERS) {
            const float* nrow = encb + (size_t)(s + 2 * WARPS) * HID;
            p1a = *(const float4*)&nrow[lane * 4];
            p1b = *(const float4*)&nrow[128 + lane * 4];
        }

        float p = a0.x * d0.x + a0.y * d0.y + a0.z * d0.z + a0.w * d0.w
                + a1.x * d1.x + a1.y * d1.y + a1.z * d1.z + a1.w * d1.w;
        #pragma unroll
        for (int o = 16; o; o >>= 1) p += __shfl_xor_sync(0xffffffffu, p, o);
        const float score = p;  // broadcast to all lanes

        if (lane == 0)
            score_out[(size_t)b * SEQ + (size_t)chunk * CHUNK + s] = score;

        const float mn    = fmaxf(m, score);
        const float alpha = __expf(m - mn);
        const float w     = __expf(score - mn);
        l = l * alpha + w;
        c0x = c0x * alpha + w * a0.x;  c0y = c0y * alpha + w * a0.y;
        c0z = c0z * alpha + w * a0.z;  c0w = c0w * alpha + w * a0.w;
        c1x = c1x * alpha + w * a1.x;  c1y = c1y * alpha + w * a1.y;
        c1z = c1z * alpha + w * a1.z;  c1w = c1w * alpha + w * a1.w;
        m = mn;
    }

    if (lane == 0) { sm[wid] = m; sl[wid] = l; }
    sctx[wid][lane * 4 + 0] = c0x;  sctx[wid][lane * 4 + 1] = c0y;
    sctx[wid][lane * 4 + 2] = c0z;  sctx[wid][lane * 4 + 3] = c0w;
    sctx[wid][128 + lane * 4 + 0] = c1x;  sctx[wid][128 + lane * 4 + 1] = c1y;
    sctx[wid][128 + lane * 4 + 2] = c1z;  sctx[wid][128 + lane * 4 + 3] = c1w;
    __syncthreads();

    // combine 8 warp partials; each thread owns one h = tid
    float M = sm[0];
    #pragma unroll
    for (int w2 = 1; w2 < WARPS; ++w2) M = fmaxf(M, sm[w2]);
    float L = 0.f, acc = 0.f;
    #pragma unroll
    for (int w2 = 0; w2 < WARPS; ++w2) {
        const float f = __expf(sm[w2] - M);
        L   += f * sl[w2];
        acc += f * sctx[w2][tid];
    }
    const int pidx = b * NSPLIT + chunk;
    if (tid == 0) { g_pm[pidx] = M; g_pl[pidx] = L; }
    g_pctx[(size_t)pidx * HID + tid] = acc;
}

// Kernel 2: combine chunk partials per batch -> context, store (M, L).
// grid BATCH, block 256 (one thread per h).
__global__ __launch_bounds__(256) void attn_pass2(float* __restrict__ ctx_out)
{
    const int b   = blockIdx.x;
    const int tid = threadIdx.x;

    float M = -CUDART_INF_F;
    #pragma unroll
    for (int k = 0; k < NSPLIT; ++k)
        M = fmaxf(M, g_pm[b * NSPLIT + k]);

    float L = 0.f, acc = 0.f;
    #pragma unroll
    for (int k = 0; k < NSPLIT; ++k) {
        const int   pidx = b * NSPLIT + k;
        const float f    = __expf(g_pm[pidx] - M);
        L   += f * g_pl[pidx];
        acc += f * g_pctx[(size_t)pidx * HID + tid];
    }
    ctx_out[b * HID + tid] = acc / L;
    if (tid == 0) { g_M[b] = M; g_L[b] = L; }
}

// Kernel 3: normalize raw scores in place -> atten_prob.
__global__ __launch_bounds__(256) void attn_pass3(float* __restrict__ prob)
{
    const int i = blockIdx.x * blockDim.x + threadIdx.x;  // 0 .. B*S-1
    const int b = i >> 13;                                // / SEQ
    const float inv_l = __frcp_rn(g_L[b]);
    prob[i] = __expf(prob[i] - g_M[b]) * inv_l;
}

extern "C" void kernel_launch(void* const* d_in, const int* in_sizes, int n_in,
                              void* d_out, int out_size)
{
    const float* dec = (const float*)d_in[0];
    const float* enc = (const float*)d_in[1];
    if (n_in >= 2 && in_sizes[0] > in_sizes[1]) {  // defensive: dec is the small one
        const float* t = dec; dec = enc; enc = t;
    }

    float* out       = (float*)d_out;
    float* prob_out  = out;                       // (B, S)
    float* ctx_out   = out + (size_t)BATCH * SEQ; // (B, H)

    dim3 g1(BATCH, NSPLIT);
    attn_pass1<<<g1, 256>>>(dec, enc, prob_out);
    attn_pass2<<<BATCH, 256>>>(ctx_out);
    attn_pass3<<<(BATCH * SEQ) / 256, 256>>>(prob_out);
}